// round 1
// baseline (speedup 1.0000x reference)
#include <cuda_runtime.h>

// Problem constants (fixed shapes from reference_code)
#define BB 2
#define SS 2048
#define DM 1024
#define NH 16
#define HD 64
#define MTOT (BB * SS)   // 4096

// Scratch for projected Q/K/V (static device arrays: allocation-free)
__device__ float g_Qp[MTOT * DM];
__device__ float g_Kp[MTOT * DM];
__device__ float g_Vp[MTOT * DM];

// ---------------------------------------------------------------------------
// Projection GEMM: C[4096,1024] = A[4096,1024] @ W[1024,1024]
// 128x128 CTA tile, BK=8, 256 threads, 8x8 per-thread microtile.
// ---------------------------------------------------------------------------
__global__ __launch_bounds__(256)
void proj_gemm(const float* __restrict__ A, const float* __restrict__ W,
               float* __restrict__ C) {
    __shared__ float As[8][128];
    __shared__ float Bs[8][128];

    const int tid = threadIdx.x;
    const int tx = tid & 15;        // 0..15 -> N microtiles
    const int ty = tid >> 4;        // 0..15 -> M microtiles
    const int bm = blockIdx.y * 128;
    const int bn = blockIdx.x * 128;

    const int arow = tid >> 1;            // 0..127
    const int acol = (tid & 1) * 4;       // 0 or 4
    const int brow = tid >> 5;            // 0..7
    const int bcol = (tid & 31) * 4;      // 0..124

    const float* Aptr = A + (size_t)(bm + arow) * DM + acol;
    const float* Wptr = W + (size_t)brow * DM + bn + bcol;

    float acc[8][8];
#pragma unroll
    for (int i = 0; i < 8; i++)
#pragma unroll
        for (int j = 0; j < 8; j++) acc[i][j] = 0.f;

    for (int k0 = 0; k0 < DM; k0 += 8) {
        float4 av = *(const float4*)(Aptr + k0);
        float4 bv = *(const float4*)(Wptr + (size_t)k0 * DM);
        As[acol + 0][arow] = av.x;
        As[acol + 1][arow] = av.y;
        As[acol + 2][arow] = av.z;
        As[acol + 3][arow] = av.w;
        *(float4*)&Bs[brow][bcol] = bv;
        __syncthreads();

#pragma unroll
        for (int k = 0; k < 8; k++) {
            float a[8], b[8];
            *(float4*)(a)     = *(const float4*)&As[k][ty * 8];
            *(float4*)(a + 4) = *(const float4*)&As[k][ty * 8 + 4];
            *(float4*)(b)     = *(const float4*)&Bs[k][tx * 8];
            *(float4*)(b + 4) = *(const float4*)&Bs[k][tx * 8 + 4];
#pragma unroll
            for (int i = 0; i < 8; i++)
#pragma unroll
                for (int j = 0; j < 8; j++) acc[i][j] += a[i] * b[j];
        }
        __syncthreads();
    }

#pragma unroll
    for (int i = 0; i < 8; i++) {
        const size_t row = (size_t)(bm + ty * 8 + i);
        float* cp = C + row * DM + bn + tx * 8;
        *(float4*)(cp)     = make_float4(acc[i][0], acc[i][1], acc[i][2], acc[i][3]);
        *(float4*)(cp + 4) = make_float4(acc[i][4], acc[i][5], acc[i][6], acc[i][7]);
    }
}

// ---------------------------------------------------------------------------
// Flash attention: one CTA per (b, h, 64-row q block). 256 threads = 8 warps.
// Warp w owns q rows w*8..w*8+7; lane owns key/out cols lane and lane+32.
// K stored transposed in smem ([d][col], lane-stride-1 reads, conflict-free);
// V stored natural ([k][c]); softmax stats kept in registers (redundant per
// lane, reduced via shfl). P tile is warp-private rows in smem.
// Smem = 3 * 16KB = 48KB exactly.
// ---------------------------------------------------------------------------
__global__ __launch_bounds__(256)
void attn_kernel(const int* __restrict__ v_mask, float* __restrict__ out) {
    __shared__ float Qst[64 * 64];   // [d][row]   (transposed Q)
    __shared__ float KVs[64 * 64];   // K phase: [d][col]; V phase: [k][c]
    __shared__ float Ps [64 * 64];   // [row][col] probabilities

    const int tid  = threadIdx.x;
    const int lane = tid & 31;
    const int w    = tid >> 5;        // 0..7
    const int q0   = blockIdx.x * 64;
    const int h    = blockIdx.y;
    const int b    = blockIdx.z;

    const float* Qg = g_Qp + (size_t)(b * SS) * DM + h * HD;
    const float* Kg = g_Kp + (size_t)(b * SS) * DM + h * HD;
    const float* Vg = g_Vp + (size_t)(b * SS) * DM + h * HD;

    // Load Q tile transposed: Qst[d][r] = Q[q0+r][d]
    {
        const int r   = tid >> 2;          // 0..63
        const int seg = (tid & 3) * 16;    // d start
        const float* src = Qg + (size_t)(q0 + r) * DM + seg;
#pragma unroll
        for (int i = 0; i < 4; i++) {
            float4 v = *(const float4*)(src + i * 4);
            const int d = seg + i * 4;
            Qst[(d + 0) * 64 + r] = v.x;
            Qst[(d + 1) * 64 + r] = v.y;
            Qst[(d + 2) * 64 + r] = v.z;
            Qst[(d + 3) * 64 + r] = v.w;
        }
    }

    float m_r[8], l_r[8], o0[8], o1[8];
#pragma unroll
    for (int i = 0; i < 8; i++) {
        m_r[i] = -3e38f; l_r[i] = 0.f; o0[i] = 0.f; o1[i] = 0.f;
    }
    __syncthreads();

    for (int kb = 0; kb < SS; kb += 64) {
        // Load K tile transposed: KVs[d][col] = K[kb+col][d]
        {
            const int r   = tid >> 2;
            const int seg = (tid & 3) * 16;
            const float* src = Kg + (size_t)(kb + r) * DM + seg;
#pragma unroll
            for (int i = 0; i < 4; i++) {
                float4 v = *(const float4*)(src + i * 4);
                const int d = seg + i * 4;
                KVs[(d + 0) * 64 + r] = v.x;
                KVs[(d + 1) * 64 + r] = v.y;
                KVs[(d + 2) * 64 + r] = v.z;
                KVs[(d + 3) * 64 + r] = v.w;
            }
        }
        const int mk0 = v_mask[b * SS + kb + lane];
        const int mk1 = v_mask[b * SS + kb + lane + 32];
        __syncthreads();

        // S = Q K^T  (per-thread: 8 rows x 2 cols)
        float s0[8], s1[8];
#pragma unroll
        for (int i = 0; i < 8; i++) { s0[i] = 0.f; s1[i] = 0.f; }
#pragma unroll 8
        for (int d = 0; d < 64; d++) {
            float a[8];
            *(float4*)(a)     = *(const float4*)&Qst[d * 64 + w * 8];
            *(float4*)(a + 4) = *(const float4*)&Qst[d * 64 + w * 8 + 4];
            const float b0 = KVs[d * 64 + lane];
            const float b1 = KVs[d * 64 + lane + 32];
#pragma unroll
            for (int i = 0; i < 8; i++) {
                s0[i] += a[i] * b0;
                s1[i] += a[i] * b1;
            }
        }
        // scale + mask (exact -1e12, matching reference's a*m - (1-m)*1e12)
#pragma unroll
        for (int i = 0; i < 8; i++) {
            s0[i] = mk0 ? s0[i] * 0.125f : -1e12f;
            s1[i] = mk1 ? s1[i] * 0.125f : -1e12f;
        }

        // Online softmax (warp-level reductions; stats redundant across lanes)
#pragma unroll
        for (int i = 0; i < 8; i++) {
            float mx = fmaxf(s0[i], s1[i]);
#pragma unroll
            for (int off = 16; off > 0; off >>= 1)
                mx = fmaxf(mx, __shfl_xor_sync(0xffffffffu, mx, off));
            const float mn   = fmaxf(m_r[i], mx);
            const float corr = __expf(m_r[i] - mn);
            const float p0   = __expf(s0[i] - mn);
            const float p1   = __expf(s1[i] - mn);
            float sum = p0 + p1;
#pragma unroll
            for (int off = 16; off > 0; off >>= 1)
                sum += __shfl_xor_sync(0xffffffffu, sum, off);
            l_r[i] = l_r[i] * corr + sum;
            m_r[i] = mn;
            o0[i] *= corr;
            o1[i] *= corr;
            Ps[(w * 8 + i) * 64 + lane]      = p0;
            Ps[(w * 8 + i) * 64 + lane + 32] = p1;
        }
        __syncthreads();   // all warps done reading K before V overwrite

        // Load V tile natural: KVs[k][c] = V[kb+k][c]
        {
            const int r   = tid >> 2;
            const int seg = (tid & 3) * 16;
            const float* src = Vg + (size_t)(kb + r) * DM + seg;
            float4* dst = (float4*)&KVs[r * 64 + seg];
#pragma unroll
            for (int i = 0; i < 4; i++) dst[i] = *(const float4*)(src + i * 4);
        }
        __syncthreads();

        // O += P @ V
#pragma unroll 4
        for (int k = 0; k < 64; k++) {
            const float b0 = KVs[k * 64 + lane];
            const float b1 = KVs[k * 64 + lane + 32];
#pragma unroll
            for (int i = 0; i < 8; i++) {
                const float p = Ps[(w * 8 + i) * 64 + k];
                o0[i] += p * b0;
                o1[i] += p * b1;
            }
        }
        __syncthreads();   // PV reads done before next K load overwrites KVs
    }

    // Epilogue: normalize and write out[b][q][h*64 + c]
#pragma unroll
    for (int i = 0; i < 8; i++) {
        const float inv = 1.0f / l_r[i];
        const int qr = q0 + w * 8 + i;
        float* op = out + (size_t)(b * SS + qr) * DM + h * HD;
        op[lane]      = o0[i] * inv;
        op[lane + 32] = o1[i] * inv;
    }
}

// ---------------------------------------------------------------------------
// Launch: 3 projection GEMMs then attention, all on the capture stream.
// ---------------------------------------------------------------------------
extern "C" void kernel_launch(void* const* d_in, const int* in_sizes, int n_in,
                              void* d_out, int out_size) {
    const float* q  = (const float*)d_in[0];
    const float* k  = (const float*)d_in[1];
    const float* v  = (const float*)d_in[2];
    const int*   vm = (const int*)  d_in[3];
    const float* Wq = (const float*)d_in[4];
    const float* Wk = (const float*)d_in[5];
    const float* Wv = (const float*)d_in[6];
    float* out = (float*)d_out;

    float *Qp = nullptr, *Kp = nullptr, *Vp = nullptr;
    cudaGetSymbolAddress((void**)&Qp, g_Qp);
    cudaGetSymbolAddress((void**)&Kp, g_Kp);
    cudaGetSymbolAddress((void**)&Vp, g_Vp);

    dim3 gg(DM / 128, MTOT / 128);     // (8, 32)
    proj_gemm<<<gg, 256>>>(q, Wq, Qp);
    proj_gemm<<<gg, 256>>>(k, Wk, Kp);
    proj_gemm<<<gg, 256>>>(v, Wv, Vp);

    dim3 ga(SS / 64, NH, BB);          // (32, 16, 2)
    attn_kernel<<<ga, 256>>>(vm, out);
}

// round 2
// speedup vs baseline: 1.0012x; 1.0012x over previous
#include <cuda_runtime.h>

// Problem constants (fixed shapes from reference_code)
#define BB 2
#define SS 2048
#define DM 1024
#define NH 16
#define HD 64
#define MTOT (BB * SS)   // 4096

// Scratch for projected Q/K/V (static device arrays: allocation-free)
__device__ float g_Qp[MTOT * DM];
__device__ float g_Kp[MTOT * DM];
__device__ float g_Vp[MTOT * DM];

// ---------------------------------------------------------------------------
// Projection GEMM: C[4096,1024] = A[4096,1024] @ W[1024,1024]
// 128x128 CTA tile, BK=8, 256 threads, 8x8 per-thread microtile.
// ---------------------------------------------------------------------------
__global__ __launch_bounds__(256)
void proj_gemm(const float* __restrict__ A, const float* __restrict__ W,
               float* __restrict__ C) {
    __shared__ float As[8][128];
    __shared__ float Bs[8][128];

    const int tid = threadIdx.x;
    const int tx = tid & 15;        // 0..15 -> N microtiles
    const int ty = tid >> 4;        // 0..15 -> M microtiles
    const int bm = blockIdx.y * 128;
    const int bn = blockIdx.x * 128;

    const int arow = tid >> 1;            // 0..127
    const int acol = (tid & 1) * 4;       // 0 or 4
    const int brow = tid >> 5;            // 0..7
    const int bcol = (tid & 31) * 4;      // 0..124

    const float* Aptr = A + (size_t)(bm + arow) * DM + acol;
    const float* Wptr = W + (size_t)brow * DM + bn + bcol;

    float acc[8][8];
#pragma unroll
    for (int i = 0; i < 8; i++)
#pragma unroll
        for (int j = 0; j < 8; j++) acc[i][j] = 0.f;

    for (int k0 = 0; k0 < DM; k0 += 8) {
        float4 av = *(const float4*)(Aptr + k0);
        float4 bv = *(const float4*)(Wptr + (size_t)k0 * DM);
        As[acol + 0][arow] = av.x;
        As[acol + 1][arow] = av.y;
        As[acol + 2][arow] = av.z;
        As[acol + 3][arow] = av.w;
        *(float4*)&Bs[brow][bcol] = bv;
        __syncthreads();

#pragma unroll
        for (int k = 0; k < 8; k++) {
            float a[8], b[8];
            *(float4*)(a)     = *(const float4*)&As[k][ty * 8];
            *(float4*)(a + 4) = *(const float4*)&As[k][ty * 8 + 4];
            *(float4*)(b)     = *(const float4*)&Bs[k][tx * 8];
            *(float4*)(b + 4) = *(const float4*)&Bs[k][tx * 8 + 4];
#pragma unroll
            for (int i = 0; i < 8; i++)
#pragma unroll
                for (int j = 0; j < 8; j++) acc[i][j] += a[i] * b[j];
        }
        __syncthreads();
    }

#pragma unroll
    for (int i = 0; i < 8; i++) {
        const size_t row = (size_t)(bm + ty * 8 + i);
        float* cp = C + row * DM + bn + tx * 8;
        *(float4*)(cp)     = make_float4(acc[i][0], acc[i][1], acc[i][2], acc[i][3]);
        *(float4*)(cp + 4) = make_float4(acc[i][4], acc[i][5], acc[i][6], acc[i][7]);
    }
}

// ---------------------------------------------------------------------------
// Flash attention: one CTA per (b, h, 64-row q block). 256 threads = 8 warps.
// Warp w owns q rows w*8..w*8+7; lane owns key/out cols lane and lane+32.
// K stored transposed in smem ([d][col], lane-stride-1 reads, conflict-free);
// V stored natural ([k][c]); softmax stats kept in registers (redundant per
// lane, reduced via shfl). P tile is warp-private rows in smem.
// Smem = 3 * 16KB = 48KB exactly.
// ---------------------------------------------------------------------------
__global__ __launch_bounds__(256)
void attn_kernel(const int* __restrict__ v_mask, float* __restrict__ out) {
    __shared__ float Qst[64 * 64];   // [d][row]   (transposed Q)
    __shared__ float KVs[64 * 64];   // K phase: [d][col]; V phase: [k][c]
    __shared__ float Ps [64 * 64];   // [row][col] probabilities

    const int tid  = threadIdx.x;
    const int lane = tid & 31;
    const int w    = tid >> 5;        // 0..7
    const int q0   = blockIdx.x * 64;
    const int h    = blockIdx.y;
    const int b    = blockIdx.z;

    const float* Qg = g_Qp + (size_t)(b * SS) * DM + h * HD;
    const float* Kg = g_Kp + (size_t)(b * SS) * DM + h * HD;
    const float* Vg = g_Vp + (size_t)(b * SS) * DM + h * HD;

    // Load Q tile transposed: Qst[d][r] = Q[q0+r][d]
    {
        const int r   = tid >> 2;          // 0..63
        const int seg = (tid & 3) * 16;    // d start
        const float* src = Qg + (size_t)(q0 + r) * DM + seg;
#pragma unroll
        for (int i = 0; i < 4; i++) {
            float4 v = *(const float4*)(src + i * 4);
            const int d = seg + i * 4;
            Qst[(d + 0) * 64 + r] = v.x;
            Qst[(d + 1) * 64 + r] = v.y;
            Qst[(d + 2) * 64 + r] = v.z;
            Qst[(d + 3) * 64 + r] = v.w;
        }
    }

    float m_r[8], l_r[8], o0[8], o1[8];
#pragma unroll
    for (int i = 0; i < 8; i++) {
        m_r[i] = -3e38f; l_r[i] = 0.f; o0[i] = 0.f; o1[i] = 0.f;
    }
    __syncthreads();

    for (int kb = 0; kb < SS; kb += 64) {
        // Load K tile transposed: KVs[d][col] = K[kb+col][d]
        {
            const int r   = tid >> 2;
            const int seg = (tid & 3) * 16;
            const float* src = Kg + (size_t)(kb + r) * DM + seg;
#pragma unroll
            for (int i = 0; i < 4; i++) {
                float4 v = *(const float4*)(src + i * 4);
                const int d = seg + i * 4;
                KVs[(d + 0) * 64 + r] = v.x;
                KVs[(d + 1) * 64 + r] = v.y;
                KVs[(d + 2) * 64 + r] = v.z;
                KVs[(d + 3) * 64 + r] = v.w;
            }
        }
        const int mk0 = v_mask[b * SS + kb + lane];
        const int mk1 = v_mask[b * SS + kb + lane + 32];
        __syncthreads();

        // S = Q K^T  (per-thread: 8 rows x 2 cols)
        float s0[8], s1[8];
#pragma unroll
        for (int i = 0; i < 8; i++) { s0[i] = 0.f; s1[i] = 0.f; }
#pragma unroll 8
        for (int d = 0; d < 64; d++) {
            float a[8];
            *(float4*)(a)     = *(const float4*)&Qst[d * 64 + w * 8];
            *(float4*)(a + 4) = *(const float4*)&Qst[d * 64 + w * 8 + 4];
            const float b0 = KVs[d * 64 + lane];
            const float b1 = KVs[d * 64 + lane + 32];
#pragma unroll
            for (int i = 0; i < 8; i++) {
                s0[i] += a[i] * b0;
                s1[i] += a[i] * b1;
            }
        }
        // scale + mask (exact -1e12, matching reference's a*m - (1-m)*1e12)
#pragma unroll
        for (int i = 0; i < 8; i++) {
            s0[i] = mk0 ? s0[i] * 0.125f : -1e12f;
            s1[i] = mk1 ? s1[i] * 0.125f : -1e12f;
        }

        // Online softmax (warp-level reductions; stats redundant across lanes)
#pragma unroll
        for (int i = 0; i < 8; i++) {
            float mx = fmaxf(s0[i], s1[i]);
#pragma unroll
            for (int off = 16; off > 0; off >>= 1)
                mx = fmaxf(mx, __shfl_xor_sync(0xffffffffu, mx, off));
            const float mn   = fmaxf(m_r[i], mx);
            const float corr = __expf(m_r[i] - mn);
            const float p0   = __expf(s0[i] - mn);
            const float p1   = __expf(s1[i] - mn);
            float sum = p0 + p1;
#pragma unroll
            for (int off = 16; off > 0; off >>= 1)
                sum += __shfl_xor_sync(0xffffffffu, sum, off);
            l_r[i] = l_r[i] * corr + sum;
            m_r[i] = mn;
            o0[i] *= corr;
            o1[i] *= corr;
            Ps[(w * 8 + i) * 64 + lane]      = p0;
            Ps[(w * 8 + i) * 64 + lane + 32] = p1;
        }
        __syncthreads();   // all warps done reading K before V overwrite

        // Load V tile natural: KVs[k][c] = V[kb+k][c]
        {
            const int r   = tid >> 2;
            const int seg = (tid & 3) * 16;
            const float* src = Vg + (size_t)(kb + r) * DM + seg;
            float4* dst = (float4*)&KVs[r * 64 + seg];
#pragma unroll
            for (int i = 0; i < 4; i++) dst[i] = *(const float4*)(src + i * 4);
        }
        __syncthreads();

        // O += P @ V
#pragma unroll 4
        for (int k = 0; k < 64; k++) {
            const float b0 = KVs[k * 64 + lane];
            const float b1 = KVs[k * 64 + lane + 32];
#pragma unroll
            for (int i = 0; i < 8; i++) {
                const float p = Ps[(w * 8 + i) * 64 + k];
                o0[i] += p * b0;
                o1[i] += p * b1;
            }
        }
        __syncthreads();   // PV reads done before next K load overwrites KVs
    }

    // Epilogue: normalize and write out[b][q][h*64 + c]
#pragma unroll
    for (int i = 0; i < 8; i++) {
        const float inv = 1.0f / l_r[i];
        const int qr = q0 + w * 8 + i;
        float* op = out + (size_t)(b * SS + qr) * DM + h * HD;
        op[lane]      = o0[i] * inv;
        op[lane + 32] = o1[i] * inv;
    }
}

// ---------------------------------------------------------------------------
// Launch: 3 projection GEMMs then attention, all on the capture stream.
// ---------------------------------------------------------------------------
extern "C" void kernel_launch(void* const* d_in, const int* in_sizes, int n_in,
                              void* d_out, int out_size) {
    const float* q  = (const float*)d_in[0];
    const float* k  = (const float*)d_in[1];
    const float* v  = (const float*)d_in[2];
    const int*   vm = (const int*)  d_in[3];
    const float* Wq = (const float*)d_in[4];
    const float* Wk = (const float*)d_in[5];
    const float* Wv = (const float*)d_in[6];
    float* out = (float*)d_out;

    float *Qp = nullptr, *Kp = nullptr, *Vp = nullptr;
    cudaGetSymbolAddress((void**)&Qp, g_Qp);
    cudaGetSymbolAddress((void**)&Kp, g_Kp);
    cudaGetSymbolAddress((void**)&Vp, g_Vp);

    dim3 gg(DM / 128, MTOT / 128);     // (8, 32)
    proj_gemm<<<gg, 256>>>(q, Wq, Qp);
    proj_gemm<<<gg, 256>>>(k, Wk, Kp);
    proj_gemm<<<gg, 256>>>(v, Wv, Vp);

    dim3 ga(SS / 64, NH, BB);          // (32, 16, 2)
    attn_kernel<<<ga, 256>>>(vm, out);
}